// round 3
// baseline (speedup 1.0000x reference)
#include <cuda_runtime.h>

// PBC neighbor-list distances. Single launch, single wave.
// Output (float32): [ d2[P] | mask_c0[P] | mask_c1[P] | ... ]
//   P = N*(N-1)/2 + S*N*N
// Block i handles: all S shifted-image rows (s, i, :) AND triangle row i.
// Each thread owns 4 consecutive j (one float4 quad), reused across all S shifts.

#define MAXC 4
#define MAXS 32

__global__ __launch_bounds__(256, 7)
void fused_kernel(const float* __restrict__ pos,
                  const float* __restrict__ cell,
                  const float* __restrict__ shifts,
                  const float* __restrict__ cutoffs,
                  int n, int S, int C, int Pc, int P,
                  float* __restrict__ out)
{
    __shared__ float svs[MAXS][4];   // padded to avoid bank conflicts

    int i   = blockIdx.x;
    int tid = threadIdx.x;

    if (tid < S) {
        float s0 = shifts[3 * tid + 0], s1 = shifts[3 * tid + 1], s2 = shifts[3 * tid + 2];
        svs[tid][0] = s0 * cell[0] + s1 * cell[3] + s2 * cell[6];
        svs[tid][1] = s0 * cell[1] + s1 * cell[4] + s2 * cell[7];
        svs[tid][2] = s0 * cell[2] + s1 * cell[5] + s2 * cell[8];
    }
    __syncthreads();

    float c2[MAXC];
#pragma unroll
    for (int c = 0; c < MAXC; c++) {
        if (c < C) { float cv = cutoffs[c]; c2[c] = cv * cv; }
        else c2[c] = 0.0f;
    }

    float pix = pos[3 * i + 0];
    float piy = pos[3 * i + 1];
    float piz = pos[3 * i + 2];

    int nn = n * n;
    int nq = n >> 2;

    // ---------------- shifted-image rows: quad per thread, all S shifts ----
    if (tid < nq) {
        const float4* __restrict__ pos4 = (const float4*)pos;
        float4 a  = pos4[3 * tid + 0];
        float4 b  = pos4[3 * tid + 1];
        float4 cc = pos4[3 * tid + 2];

        // rij = pi - pj for the 4 atoms of this quad (reused for every shift)
        float rx0 = pix - a.x,  ry0 = piy - a.y,  rz0 = piz - a.z;
        float rx1 = pix - a.w,  ry1 = piy - b.x,  rz1 = piz - b.y;
        float rx2 = pix - b.z,  ry2 = piy - b.w,  rz2 = piz - cc.x;
        float rx3 = pix - cc.y, ry3 = piy - cc.z, rz3 = piz - cc.w;

        int base = Pc + i * n + 4 * tid;   // rowbase for s=0

        for (int s = 0; s < S; s++) {
            float svx = svs[s][0], svy = svs[s][1], svz = svs[s][2];

            float dx, dy, dz;
            float4 dv;
            dx = rx0 + svx; dy = ry0 + svy; dz = rz0 + svz;
            dv.x = dx * dx + dy * dy + dz * dz;
            dx = rx1 + svx; dy = ry1 + svy; dz = rz1 + svz;
            dv.y = dx * dx + dy * dy + dz * dz;
            dx = rx2 + svx; dy = ry2 + svy; dz = rz2 + svz;
            dv.z = dx * dx + dy * dy + dz * dz;
            dx = rx3 + svx; dy = ry3 + svy; dz = rz3 + svz;
            dv.w = dx * dx + dy * dy + dz * dz;

            int addr = base + s * nn;
            *(float4*)(out + addr) = dv;

#pragma unroll
            for (int c = 0; c < MAXC; c++) {
                if (c < C) {
                    float4 mv;
                    mv.x = (dv.x < c2[c]) ? 1.0f : 0.0f;
                    mv.y = (dv.y < c2[c]) ? 1.0f : 0.0f;
                    mv.z = (dv.z < c2[c]) ? 1.0f : 0.0f;
                    mv.w = (dv.w < c2[c]) ? 1.0f : 0.0f;
                    *(float4*)(out + P + c * P + addr) = mv;
                }
            }
        }
    }

    // scalar remainder of each shifted row (n % 4 != 0; not hit for n=1000)
    for (int j = (nq << 2) + tid; j < n; j += blockDim.x) {
        float rx = pix - pos[3 * j + 0];
        float ry = piy - pos[3 * j + 1];
        float rz = piz - pos[3 * j + 2];
        for (int s = 0; s < S; s++) {
            float dx = rx + svs[s][0];
            float dy = ry + svs[s][1];
            float dz = rz + svs[s][2];
            float d2 = dx * dx + dy * dy + dz * dz;
            int addr = Pc + (s * n + i) * n + j;
            out[addr] = d2;
#pragma unroll
            for (int c = 0; c < MAXC; c++) {
                if (c < C)
                    out[P + c * P + addr] = (d2 < c2[c]) ? 1.0f : 0.0f;
            }
        }
    }

    // ---------------- triangle row i: pairs (i, j), j > i --------------------
    // row start offset in packed upper triangle
    int off = i * (2 * n - i - 1) / 2;
    for (int j = i + 1 + tid; j < n; j += blockDim.x) {
        float dx = pix - pos[3 * j + 0];
        float dy = piy - pos[3 * j + 1];
        float dz = piz - pos[3 * j + 2];
        float d2 = dx * dx + dy * dy + dz * dz;
        int p = off + (j - i - 1);
        out[p] = d2;
#pragma unroll
        for (int c = 0; c < MAXC; c++) {
            if (c < C)
                out[P + c * P + p] = (d2 < c2[c]) ? 1.0f : 0.0f;
        }
    }
}

extern "C" void kernel_launch(void* const* d_in, const int* in_sizes, int n_in,
                              void* d_out, int out_size)
{
    const float* pos     = (const float*)d_in[0];  // [N,3]
    const float* cell    = (const float*)d_in[1];  // [3,3]
    const float* shifts  = (const float*)d_in[2];  // [S,3]
    const float* cutoffs = (const float*)d_in[3];  // [C]

    int n = in_sizes[0] / 3;
    int S = in_sizes[2] / 3;
    int C = in_sizes[3];
    if (C > MAXC) C = MAXC;
    if (S > MAXS) S = MAXS;   // problem instance has S=13

    int Pc = n * (n - 1) / 2;
    int P  = Pc + S * n * n;

    fused_kernel<<<n, 256>>>(pos, cell, shifts, cutoffs, n, S, C, Pc, P,
                             (float*)d_out);
}

// round 4
// speedup vs baseline: 1.1848x; 1.1848x over previous
#include <cuda_runtime.h>

// PBC neighbor-list distances. Single fused launch.
// Output (float32): [ d2[P] | mask_c0[P] | mask_c1[P] | ... ]
//   P = N*(N-1)/2 + S*N*N
// gridDim = (N, S+1):
//   y = s < S : shifted-image row (s, i, :) — one float4 quad per thread
//   y = S     : triangle row i — scalar strided (only 3.7% of bytes; keep lean)
// All offsets fit in int32 (3P ~ 40.5M).

template <int C>
__global__ __launch_bounds__(256, 8)
void fused_kernel(const float* __restrict__ pos,
                  const float* __restrict__ cell,
                  const float* __restrict__ shifts,
                  const float* __restrict__ cutoffs,
                  int n, int S, int Pc, int P,
                  float* __restrict__ out)
{
    int i   = blockIdx.x;
    int s   = blockIdx.y;
    int tid = threadIdx.x;

    float c2[C];
#pragma unroll
    for (int c = 0; c < C; c++) { float cv = cutoffs[c]; c2[c] = cv * cv; }

    float pix = pos[3 * i + 0];
    float piy = pos[3 * i + 1];
    float piz = pos[3 * i + 2];

    if (s < S) {
        // ---------------- shifted-image row (s, i, :) ----------------
        float s0 = shifts[3 * s + 0], s1 = shifts[3 * s + 1], s2 = shifts[3 * s + 2];
        float svx = s0 * cell[0] + s1 * cell[3] + s2 * cell[6];
        float svy = s0 * cell[1] + s1 * cell[4] + s2 * cell[7];
        float svz = s0 * cell[2] + s1 * cell[5] + s2 * cell[8];

        int rowbase = Pc + (s * n + i) * n;
        const float4* __restrict__ pos4 = (const float4*)pos;
        int nq = n >> 2;

        for (int q = tid; q < nq; q += blockDim.x) {
            float4 a  = pos4[3 * q + 0];
            float4 b  = pos4[3 * q + 1];
            float4 cc = pos4[3 * q + 2];

            float dx, dy, dz;
            float4 dv;
            // keep reference FP ordering: (pi - pj) + sv
            dx = (pix - a.x) + svx;  dy = (piy - a.y) + svy;  dz = (piz - a.z) + svz;
            dv.x = dx * dx + dy * dy + dz * dz;
            dx = (pix - a.w) + svx;  dy = (piy - b.x) + svy;  dz = (piz - b.y) + svz;
            dv.y = dx * dx + dy * dy + dz * dz;
            dx = (pix - b.z) + svx;  dy = (piy - b.w) + svy;  dz = (piz - cc.x) + svz;
            dv.z = dx * dx + dy * dy + dz * dz;
            dx = (pix - cc.y) + svx; dy = (piy - cc.z) + svy; dz = (piz - cc.w) + svz;
            dv.w = dx * dx + dy * dy + dz * dz;

            int addr = rowbase + 4 * q;
            *(float4*)(out + addr) = dv;

#pragma unroll
            for (int c = 0; c < C; c++) {
                float4 mv;
                mv.x = (dv.x < c2[c]) ? 1.0f : 0.0f;
                mv.y = (dv.y < c2[c]) ? 1.0f : 0.0f;
                mv.z = (dv.z < c2[c]) ? 1.0f : 0.0f;
                mv.w = (dv.w < c2[c]) ? 1.0f : 0.0f;
                *(float4*)(out + P + c * P + addr) = mv;
            }
        }

        // scalar remainder (n % 4 != 0; not hit for n=1000)
        for (int j = (nq << 2) + tid; j < n; j += blockDim.x) {
            float dx = (pix - pos[3 * j + 0]) + svx;
            float dy = (piy - pos[3 * j + 1]) + svy;
            float dz = (piz - pos[3 * j + 2]) + svz;
            float d2 = dx * dx + dy * dy + dz * dz;
            int addr = rowbase + j;
            out[addr] = d2;
#pragma unroll
            for (int c = 0; c < C; c++)
                out[P + c * P + addr] = (d2 < c2[c]) ? 1.0f : 0.0f;
        }
    } else {
        // ---------------- triangle row i: pairs (i, j), j > i ----------------
        int off = i * (2 * n - i - 1) / 2;   // packed row start
        for (int j = i + 1 + tid; j < n; j += blockDim.x) {
            float dx = pix - pos[3 * j + 0];
            float dy = piy - pos[3 * j + 1];
            float dz = piz - pos[3 * j + 2];
            float d2 = dx * dx + dy * dy + dz * dz;
            int p = off + (j - i - 1);
            out[p] = d2;
#pragma unroll
            for (int c = 0; c < C; c++)
                out[P + c * P + p] = (d2 < c2[c]) ? 1.0f : 0.0f;
        }
    }
}

extern "C" void kernel_launch(void* const* d_in, const int* in_sizes, int n_in,
                              void* d_out, int out_size)
{
    const float* pos     = (const float*)d_in[0];  // [N,3]
    const float* cell    = (const float*)d_in[1];  // [3,3]
    const float* shifts  = (const float*)d_in[2];  // [S,3]
    const float* cutoffs = (const float*)d_in[3];  // [C]

    int n = in_sizes[0] / 3;
    int S = in_sizes[2] / 3;
    int C = in_sizes[3];

    int Pc = n * (n - 1) / 2;
    int P  = Pc + S * n * n;

    dim3 grid(n, S + 1);
    float* out = (float*)d_out;

    switch (C) {
        case 1: fused_kernel<1><<<grid, 256>>>(pos, cell, shifts, cutoffs, n, S, Pc, P, out); break;
        case 2: fused_kernel<2><<<grid, 256>>>(pos, cell, shifts, cutoffs, n, S, Pc, P, out); break;
        case 3: fused_kernel<3><<<grid, 256>>>(pos, cell, shifts, cutoffs, n, S, Pc, P, out); break;
        default: fused_kernel<4><<<grid, 256>>>(pos, cell, shifts, cutoffs, n, S, Pc, P, out); break;
    }
}